// round 4
// baseline (speedup 1.0000x reference)
#include <cuda_runtime.h>
#include <cuda_bf16.h>
#include <cstdint>

// Problem constants
#define TT    2048
#define BB    32
#define HHID  512
#define KK    1024          // concat input dim [x|h] or [h1|h2]
#define KPAD  1032          // padded K stride in SMEM (conflict-free)
#define NPL   64            // CTAs per layer
#define NCTA  128           // total persistent CTAs
#define BH    (BB*HHID)     // 16384 elements per timestep slice

// ---------------- device global scratch -------------------------------------
__device__ __nv_bfloat16 g_X[(size_t)TT * BH];                 // gathered embeddings
__device__ __nv_bfloat16 g_H[2][(size_t)(TT + 1) * BH];        // h per layer per step
__device__ __nv_bfloat16 g_W[(size_t)NCTA * 32 * KK];          // per-CTA weight slices
__device__ float         g_bias[NCTA * 32];
__device__ int           g_flagT[2][64];                       // last published t, per layer per slice-CTA

// ---------------- helpers ---------------------------------------------------
__device__ __forceinline__ void mma16816(float* c, const uint32_t* a,
                                         uint32_t b0, uint32_t b1) {
    asm volatile(
        "mma.sync.aligned.m16n8k16.row.col.f32.bf16.bf16.f32 "
        "{%0,%1,%2,%3},{%4,%5,%6,%7},{%8,%9},{%0,%1,%2,%3};\n"
        : "+f"(c[0]), "+f"(c[1]), "+f"(c[2]), "+f"(c[3])
        : "r"(a[0]), "r"(a[1]), "r"(a[2]), "r"(a[3]), "r"(b0), "r"(b1));
}

__device__ __forceinline__ float sigmoidf_(float x) {
    return 1.0f / (1.0f + __expf(-x));
}

__device__ __forceinline__ int ld_acq(const int* p) {
    int v;
    asm volatile("ld.acquire.gpu.global.s32 %0, [%1];" : "=r"(v) : "l"(p) : "memory");
    return v;
}
__device__ __forceinline__ void st_rel(int* p, int v) {
    asm volatile("st.release.gpu.global.s32 [%0], %1;" :: "l"(p), "r"(v) : "memory");
}
// warp-collective wait on 8 per-producer flags (one 32B sector): lanes 0..7 poll
__device__ __forceinline__ void wait_flags8(const int* p, int t, int lane) {
    int v = 0x7fffffff;
    if (lane < 8) v = ld_acq(p + lane);
    while (__any_sync(0xffffffffu, v < t)) {
        if (lane < 8) v = ld_acq(p + lane);
    }
    __syncwarp();
}
__device__ __forceinline__ void cp16(uint32_t dst_smem, const void* src) {
    asm volatile("cp.async.cg.shared.global [%0], [%1], 16;\n" :: "r"(dst_smem), "l"(src));
}
__device__ __forceinline__ void cp_commit() {
    asm volatile("cp.async.commit_group;\n" ::: "memory");
}
template<int N>
__device__ __forceinline__ void cp_wait() {
    asm volatile("cp.async.wait_group %0;\n" :: "n"(N) : "memory");
}

// ---------------- prep: reorganize weights to per-CTA bf16 slices -----------
__global__ void prep_w_kernel(const float* __restrict__ w_ih,
                              const float* __restrict__ w_hh,
                              const float* __restrict__ b_ih,
                              const float* __restrict__ b_hh) {
    int idx = blockIdx.x * blockDim.x + threadIdx.x;
    if (idx >= NCTA * 32 * KK) return;
    int k   = idx & 1023;
    int r   = (idx >> 10) & 31;
    int cta = idx >> 15;
    int L = cta >> 6, s = cta & 63;
    int g = r >> 3,  j = r & 7;
    int col = g * 512 + s * 8 + j;
    size_t base = ((size_t)L * 2048 + col) * 512;
    float w = (k < 512) ? w_ih[base + k] : w_hh[base + (k - 512)];
    g_W[idx] = __float2bfloat16(w);
    if (k == 0) g_bias[cta * 32 + r] = b_ih[L * 2048 + col] + b_hh[L * 2048 + col];
}

// ---------------- prep: embedding gather to bf16 [t][b][k] ------------------
__global__ void gather_x_kernel(const int* __restrict__ tokens,
                                const float* __restrict__ emb) {
    int idx = blockIdx.x * blockDim.x + threadIdx.x;
    if (idx >= TT * BB * 64) return;
    int k8 = idx & 63;
    int b  = (idx >> 6) & 31;
    int t  = idx >> 11;
    int tok = tokens[b * TT + t];
    const float* e = emb + (size_t)tok * 512 + k8 * 8;
    __nv_bfloat16 v[8];
#pragma unroll
    for (int i = 0; i < 8; ++i) v[i] = __float2bfloat16(e[i]);
    *(uint4*)(g_X + ((size_t)t * BB + b) * 512 + k8 * 8) = *(uint4*)v;
}

// ---------------- prep: init state ------------------------------------------
__global__ void init_kernel() {
    int idx = blockIdx.x * blockDim.x + threadIdx.x;
    if (idx < BH) {
        __nv_bfloat16 z = __float2bfloat16(0.0f);
        g_H[0][idx] = z;
        g_H[1][idx] = z;
    }
    if (idx < 128) ((int*)g_flagT)[idx] = 0;
}

// ---------------- the persistent LSTM kernel --------------------------------
// 128 CTAs (64/layer), 256 threads. Weights in registers.
// Warp ks owns k-columns [ks*64, ks*64+64); per-warp fine-grained flag waits
// on exactly the 8 producer CTAs that write those columns.
#define SMEM_ACT_BYTES (32 * KPAD * 2)
#define SMEM_BYTES     (SMEM_ACT_BYTES + 8 * 32 * 33 * 4)

__global__ void __launch_bounds__(256, 1) lstm_kernel() {
    extern __shared__ unsigned char smem_raw[];
    __nv_bfloat16* Ash  = (__nv_bfloat16*)smem_raw;
    float*         Psum = (float*)(smem_raw + SMEM_ACT_BYTES);
    uint32_t ash_s = (uint32_t)__cvta_generic_to_shared(Ash);

    const int tid = threadIdx.x;
    const int cta = blockIdx.x;
    const int L = cta >> 6;
    const int s = cta & 63;

    const int ks   = tid >> 5;          // warp = k-slice
    const int lane = tid & 31;
    const int gid  = lane >> 2;
    const int t4   = lane & 3;

    // ---- load weight fragments into registers (once) ----
    const __nv_bfloat16* wsrc = g_W + (size_t)cta * 32 * KK;
    uint32_t areg[2][4][2][4];          // [half][kc][mb][frag]
#pragma unroll
    for (int half = 0; half < 2; ++half)
#pragma unroll
        for (int kc = 0; kc < 4; ++kc) {
            int k0 = half * 512 + ks * 64 + kc * 16 + t4 * 2;
#pragma unroll
            for (int mb = 0; mb < 2; ++mb) {
                int r = mb * 16 + gid;
                areg[half][kc][mb][0] = *(const uint32_t*)(wsrc + r * KK + k0);
                areg[half][kc][mb][1] = *(const uint32_t*)(wsrc + (r + 8) * KK + k0);
                areg[half][kc][mb][2] = *(const uint32_t*)(wsrc + r * KK + k0 + 8);
                areg[half][kc][mb][3] = *(const uint32_t*)(wsrc + (r + 8) * KK + k0 + 8);
            }
        }

    // ---- bias + cell state in registers ----
    const int bact = tid >> 3, jact = tid & 7;      // tid = b*8 + j
    float bias_r[4];
#pragma unroll
    for (int g = 0; g < 4; ++g) bias_r[g] = g_bias[cta * 32 + g * 8 + jact];
    float c_reg = 0.0f;

    int* flags_own = &g_flagT[L][0];
    int* flags_l0  = &g_flagT[0][0];
    const int* fown = flags_own + ks * 8;   // this warp's 8 h-producers
    const int* fl0  = flags_l0  + ks * 8;   // this warp's 8 x-producers (L1)

    // per-warp cp.async lane mapping
    const int c8   = lane & 7;
    const int brow = lane >> 3;
    const int kcol = ks * 64 + c8 * 8;
    const int xdst = (brow * KPAD + kcol);
    const int hdst = (brow * KPAD + 512 + kcol);

    // ---- prologue: prefetch x(1) ----
    if (L == 1) wait_flags8(fl0, 1, lane);
    {
        const __nv_bfloat16* srcx = (L == 0) ? g_X : (g_H[0] + (size_t)BH);
#pragma unroll
        for (int r = 0; r < 8; ++r)
            cp16(ash_s + (xdst + r * 4 * KPAD) * 2, srcx + (brow + r * 4) * 512 + kcol);
        cp_commit();
    }

    for (int t = 1; t <= TT; ++t) {
        float acc[2][4][4];
#pragma unroll
        for (int mb = 0; mb < 2; ++mb)
#pragma unroll
            for (int nt = 0; nt < 4; ++nt)
#pragma unroll
                for (int i = 0; i < 4; ++i) acc[mb][nt][i] = 0.0f;

        // ---- x(t) ready (prefetched) ----
        cp_wait<0>();
        __syncwarp();

        // ---- x-mma kc 0..1 (overlaps producers' publish propagation) ----
#pragma unroll
        for (int kc = 0; kc < 2; ++kc) {
            int k0 = ks * 64 + kc * 16 + t4 * 2;
#pragma unroll
            for (int nt = 0; nt < 4; ++nt) {
                const __nv_bfloat16* bp = Ash + (nt * 8 + gid) * KPAD + k0;
                uint32_t b0 = *(const uint32_t*)bp;
                uint32_t b1 = *(const uint32_t*)(bp + 8);
                mma16816(acc[0][nt], areg[0][kc][0], b0, b1);
                mma16816(acc[1][nt], areg[0][kc][1], b0, b1);
            }
        }

        // ---- wait own-layer h(t-1) producers (8 flags), issue h load ----
        wait_flags8(fown, t - 1, lane);
        {
            const __nv_bfloat16* srch = g_H[L] + (size_t)(t - 1) * BH;
#pragma unroll
            for (int r = 0; r < 8; ++r)
                cp16(ash_s + (hdst + r * 4 * KPAD) * 2, srch + (brow + r * 4) * 512 + kcol);
            cp_commit();
        }

        // ---- x-mma kc 2..3 (hides h load latency) ----
#pragma unroll
        for (int kc = 2; kc < 4; ++kc) {
            int k0 = ks * 64 + kc * 16 + t4 * 2;
#pragma unroll
            for (int nt = 0; nt < 4; ++nt) {
                const __nv_bfloat16* bp = Ash + (nt * 8 + gid) * KPAD + k0;
                uint32_t b0 = *(const uint32_t*)bp;
                uint32_t b1 = *(const uint32_t*)(bp + 8);
                mma16816(acc[0][nt], areg[0][kc][0], b0, b1);
                mma16816(acc[1][nt], areg[0][kc][1], b0, b1);
            }
        }

        // ---- h-half MMA ----
        cp_wait<0>();
        __syncwarp();
#pragma unroll
        for (int kc = 0; kc < 4; ++kc) {
            int k0 = 512 + ks * 64 + kc * 16 + t4 * 2;
#pragma unroll
            for (int nt = 0; nt < 4; ++nt) {
                const __nv_bfloat16* bp = Ash + (nt * 8 + gid) * KPAD + k0;
                uint32_t b0 = *(const uint32_t*)bp;
                uint32_t b1 = *(const uint32_t*)(bp + 8);
                mma16816(acc[0][nt], areg[1][kc][0], b0, b1);
                mma16816(acc[1][nt], areg[1][kc][1], b0, b1);
            }
        }

        // ---- write k-partials ----
#pragma unroll
        for (int mb = 0; mb < 2; ++mb)
#pragma unroll
            for (int nt = 0; nt < 4; ++nt) {
                int r = ks * 32 + mb * 16 + gid;
                int c = nt * 8 + t4 * 2;
                Psum[r * 33 + c]           = acc[mb][nt][0];
                Psum[r * 33 + c + 1]       = acc[mb][nt][1];
                Psum[(r + 8) * 33 + c]     = acc[mb][nt][2];
                Psum[(r + 8) * 33 + c + 1] = acc[mb][nt][3];
            }

        // ---- prefetch x(t+1); latency hides under reduce+publish ----
        if (t < TT) {
            if (L == 1) wait_flags8(fl0, t + 1, lane);
            const __nv_bfloat16* srcx = (L == 0) ? (g_X + (size_t)t * BH)
                                                 : (g_H[0] + (size_t)(t + 1) * BH);
#pragma unroll
            for (int r = 0; r < 8; ++r)
                cp16(ash_s + (xdst + r * 4 * KPAD) * 2, srcx + (brow + r * 4) * 512 + kcol);
            cp_commit();
        }
        __syncthreads();

        // ---- reduce + cell update: thread (b = tid>>3, j = tid&7) ----
        {
            float gv[4];
#pragma unroll
            for (int g = 0; g < 4; ++g) {
                int row = g * 8 + jact;
                float v = bias_r[g];
#pragma unroll
                for (int w = 0; w < 8; ++w) v += Psum[(w * 32 + row) * 33 + bact];
                gv[g] = v;
            }
            float ig = sigmoidf_(gv[0]);
            float fg = sigmoidf_(gv[1]);
            float gg = tanhf(gv[2]);
            float og = sigmoidf_(gv[3]);
            c_reg = fg * c_reg + ig * gg;
            float h_new = og * tanhf(c_reg);
            g_H[L][(size_t)t * BH + bact * 512 + s * 8 + jact] = __float2bfloat16(h_new);
        }
        __syncthreads();   // all h stores done (also protects Psum reuse)

        // ---- publish: per-CTA monotonic flag ----
        if (tid == 0) st_rel(&flags_own[s], t);
    }
}

// ---------------- final FC + sigmoid ----------------------------------------
__global__ void fc_kernel(const float* __restrict__ fc_w,
                          const float* __restrict__ fc_b,
                          float* __restrict__ out) {
    __shared__ float part[512];
    int tid = threadIdx.x;                 // 512 threads: (b, o, p8)
    int p = tid & 7, o = (tid >> 3) & 1, b = tid >> 4;
    const __nv_bfloat16* h = g_H[1] + (size_t)TT * BH + b * 512 + p * 64;
    const float* w = fc_w + o * 512 + p * 64;
    float sum = 0.0f;
#pragma unroll
    for (int u = 0; u < 64; ++u) sum += __bfloat162float(h[u]) * w[u];
    part[tid] = sum;
    __syncthreads();
    if (p == 0) {
        float v = fc_b[o];
#pragma unroll
        for (int q = 0; q < 8; ++q) v += part[tid + q];
        out[b * 2 + o] = sigmoidf_(v);
    }
}

// ---------------- launch -----------------------------------------------------
extern "C" void kernel_launch(void* const* d_in, const int* in_sizes, int n_in,
                              void* d_out, int out_size) {
    const int*   tokens = (const int*)d_in[0];
    const float* emb    = (const float*)d_in[1];
    const float* w_ih   = (const float*)d_in[2];
    const float* w_hh   = (const float*)d_in[3];
    const float* b_ih   = (const float*)d_in[4];
    const float* b_hh   = (const float*)d_in[5];
    const float* fc_w   = (const float*)d_in[6];
    const float* fc_b   = (const float*)d_in[7];
    float* out = (float*)d_out;

    cudaFuncSetAttribute(lstm_kernel, cudaFuncAttributeMaxDynamicSharedMemorySize, SMEM_BYTES);

    prep_w_kernel<<<16384, 256>>>(w_ih, w_hh, b_ih, b_hh);
    gather_x_kernel<<<16384, 256>>>(tokens, emb);
    init_kernel<<<64, 256>>>();
    lstm_kernel<<<NCTA, 256, SMEM_BYTES>>>();
    fc_kernel<<<1, 512>>>(fc_w, fc_b, out);
}

// round 5
// speedup vs baseline: 1.0706x; 1.0706x over previous
#include <cuda_runtime.h>
#include <cuda_bf16.h>
#include <cstdint>

// Problem constants
#define TT    2048
#define BB    32
#define HHID  512
#define KK    1024          // concat input dim [x|h] or [h1|h2]
#define KPAD  1032          // padded K stride in SMEM (conflict-free)
#define NPL   64            // CTAs per layer
#define NCTA  128           // total persistent CTAs
#define BH    (BB*HHID)     // 16384 elements per timestep slice

// ---------------- device global scratch -------------------------------------
__device__ __nv_bfloat16 g_X[(size_t)TT * BH];                 // gathered embeddings
__device__ __nv_bfloat16 g_H[2][(size_t)(TT + 1) * BH];        // h per layer per step
__device__ __nv_bfloat16 g_W[(size_t)NCTA * 32 * KK];          // per-CTA weight slices
__device__ float         g_bias[NCTA * 32];
__device__ int           g_flagT[2][64];                       // last published t per (layer, slice)

// ---------------- helpers ---------------------------------------------------
__device__ __forceinline__ void mma16816(float* c, const uint32_t* a,
                                         uint32_t b0, uint32_t b1) {
    asm volatile(
        "mma.sync.aligned.m16n8k16.row.col.f32.bf16.bf16.f32 "
        "{%0,%1,%2,%3},{%4,%5,%6,%7},{%8,%9},{%0,%1,%2,%3};\n"
        : "+f"(c[0]), "+f"(c[1]), "+f"(c[2]), "+f"(c[3])
        : "r"(a[0]), "r"(a[1]), "r"(a[2]), "r"(a[3]), "r"(b0), "r"(b1));
}

__device__ __forceinline__ float sigmoidf_(float x) {
    return 1.0f / (1.0f + __expf(-x));
}

__device__ __forceinline__ int ld_acq(const int* p) {
    int v;
    asm volatile("ld.acquire.gpu.global.s32 %0, [%1];" : "=r"(v) : "l"(p) : "memory");
    return v;
}
__device__ __forceinline__ void st_rel(int* p, int v) {
    asm volatile("st.release.gpu.global.s32 [%0], %1;" :: "l"(p), "r"(v) : "memory");
}
// warp-collective wait on 8 per-producer flags (one 32B sector), THROTTLED.
__device__ __forceinline__ void wait_flags8(const int* p, int t, int lane) {
    int v = 0x7fffffff;
    if (lane < 8) v = ld_acq(p + lane);
    while (__any_sync(0xffffffffu, v < t)) {
        __nanosleep(32);
        if (lane < 8) v = ld_acq(p + lane);
    }
    __syncwarp();
}
__device__ __forceinline__ void cp16(uint32_t dst_smem, const void* src) {
    asm volatile("cp.async.cg.shared.global [%0], [%1], 16;\n" :: "r"(dst_smem), "l"(src));
}
__device__ __forceinline__ void cp_commit() {
    asm volatile("cp.async.commit_group;\n" ::: "memory");
}
template<int N>
__device__ __forceinline__ void cp_wait() {
    asm volatile("cp.async.wait_group %0;\n" :: "n"(N) : "memory");
}

// ---------------- prep: reorganize weights to per-CTA bf16 slices -----------
__global__ void prep_w_kernel(const float* __restrict__ w_ih,
                              const float* __restrict__ w_hh,
                              const float* __restrict__ b_ih,
                              const float* __restrict__ b_hh) {
    int idx = blockIdx.x * blockDim.x + threadIdx.x;
    if (idx >= NCTA * 32 * KK) return;
    int k   = idx & 1023;
    int r   = (idx >> 10) & 31;
    int cta = idx >> 15;
    int L = cta >> 6, s = cta & 63;
    int g = r >> 3,  j = r & 7;
    int col = g * 512 + s * 8 + j;
    size_t base = ((size_t)L * 2048 + col) * 512;
    float w = (k < 512) ? w_ih[base + k] : w_hh[base + (k - 512)];
    g_W[idx] = __float2bfloat16(w);
    if (k == 0) g_bias[cta * 32 + r] = b_ih[L * 2048 + col] + b_hh[L * 2048 + col];
}

// ---------------- prep: embedding gather to bf16 [t][b][k] ------------------
__global__ void gather_x_kernel(const int* __restrict__ tokens,
                                const float* __restrict__ emb) {
    int idx = blockIdx.x * blockDim.x + threadIdx.x;
    if (idx >= TT * BB * 64) return;
    int k8 = idx & 63;
    int b  = (idx >> 6) & 31;
    int t  = idx >> 11;
    int tok = tokens[b * TT + t];
    const float* e = emb + (size_t)tok * 512 + k8 * 8;
    __nv_bfloat16 v[8];
#pragma unroll
    for (int i = 0; i < 8; ++i) v[i] = __float2bfloat16(e[i]);
    *(uint4*)(g_X + ((size_t)t * BB + b) * 512 + k8 * 8) = *(uint4*)v;
}

// ---------------- prep: init state ------------------------------------------
__global__ void init_kernel() {
    int idx = blockIdx.x * blockDim.x + threadIdx.x;
    if (idx < BH) {
        __nv_bfloat16 z = __float2bfloat16(0.0f);
        g_H[0][idx] = z;
        g_H[1][idx] = z;
    }
    if (idx < 128) ((int*)g_flagT)[idx] = 0;
}

// ---------------- the persistent LSTM kernel --------------------------------
// 128 CTAs (64/layer), 256 threads. Weights in registers.
// Producer: one st.release to its own flag (no atomic serialization).
// Consumer warp ks: throttled poll of exactly its 8 producer flags (1 sector).
#define SMEM_ACT_BYTES (32 * KPAD * 2)
#define SMEM_BYTES     (SMEM_ACT_BYTES + 8 * 32 * 33 * 4)

__global__ void __launch_bounds__(256, 1) lstm_kernel() {
    extern __shared__ unsigned char smem_raw[];
    __nv_bfloat16* Ash  = (__nv_bfloat16*)smem_raw;
    float*         Psum = (float*)(smem_raw + SMEM_ACT_BYTES);
    uint32_t ash_s = (uint32_t)__cvta_generic_to_shared(Ash);

    const int tid = threadIdx.x;
    const int cta = blockIdx.x;
    const int L = cta >> 6;
    const int s = cta & 63;

    const int ks   = tid >> 5;          // warp = k-slice
    const int lane = tid & 31;
    const int gid  = lane >> 2;
    const int t4   = lane & 3;

    // ---- load weight fragments into registers (once) ----
    const __nv_bfloat16* wsrc = g_W + (size_t)cta * 32 * KK;
    uint32_t areg[2][4][2][4];          // [half][kc][mb][frag]
#pragma unroll
    for (int half = 0; half < 2; ++half)
#pragma unroll
        for (int kc = 0; kc < 4; ++kc) {
            int k0 = half * 512 + ks * 64 + kc * 16 + t4 * 2;
#pragma unroll
            for (int mb = 0; mb < 2; ++mb) {
                int r = mb * 16 + gid;
                areg[half][kc][mb][0] = *(const uint32_t*)(wsrc + r * KK + k0);
                areg[half][kc][mb][1] = *(const uint32_t*)(wsrc + (r + 8) * KK + k0);
                areg[half][kc][mb][2] = *(const uint32_t*)(wsrc + r * KK + k0 + 8);
                areg[half][kc][mb][3] = *(const uint32_t*)(wsrc + (r + 8) * KK + k0 + 8);
            }
        }

    // ---- bias + cell state in registers ----
    const int bact = tid >> 3, jact = tid & 7;      // tid = b*8 + j
    float bias_r[4];
#pragma unroll
    for (int g = 0; g < 4; ++g) bias_r[g] = g_bias[cta * 32 + g * 8 + jact];
    float c_reg = 0.0f;

    int* flags_own = &g_flagT[L][0];
    int* flags_l0  = &g_flagT[0][0];
    const int* fown = flags_own + ks * 8;   // this warp's 8 h-producers
    const int* fl0  = flags_l0  + ks * 8;   // this warp's 8 x-producers (L1)

    // per-warp cp.async lane mapping
    const int c8   = lane & 7;
    const int brow = lane >> 3;
    const int kcol = ks * 64 + c8 * 8;
    const int xdst = (brow * KPAD + kcol);
    const int hdst = (brow * KPAD + 512 + kcol);

    // ---- prologue: prefetch x(1) ----
    if (L == 1) wait_flags8(fl0, 1, lane);
    {
        const __nv_bfloat16* srcx = (L == 0) ? g_X : (g_H[0] + (size_t)BH);
#pragma unroll
        for (int r = 0; r < 8; ++r)
            cp16(ash_s + (xdst + r * 4 * KPAD) * 2, srcx + (brow + r * 4) * 512 + kcol);
        cp_commit();
    }

    for (int t = 1; t <= TT; ++t) {
        float acc[2][4][4];
#pragma unroll
        for (int mb = 0; mb < 2; ++mb)
#pragma unroll
            for (int nt = 0; nt < 4; ++nt)
#pragma unroll
                for (int i = 0; i < 4; ++i) acc[mb][nt][i] = 0.0f;

        // ---- x(t) ready (prefetched) ----
        cp_wait<0>();
        __syncwarp();

        // ---- x-mma kc 0..1 (overlaps producers' publish propagation) ----
#pragma unroll
        for (int kc = 0; kc < 2; ++kc) {
            int k0 = ks * 64 + kc * 16 + t4 * 2;
#pragma unroll
            for (int nt = 0; nt < 4; ++nt) {
                const __nv_bfloat16* bp = Ash + (nt * 8 + gid) * KPAD + k0;
                uint32_t b0 = *(const uint32_t*)bp;
                uint32_t b1 = *(const uint32_t*)(bp + 8);
                mma16816(acc[0][nt], areg[0][kc][0], b0, b1);
                mma16816(acc[1][nt], areg[0][kc][1], b0, b1);
            }
        }

        // ---- wait own-layer h(t-1) producers (8 flags, throttled), issue h ----
        wait_flags8(fown, t - 1, lane);
        {
            const __nv_bfloat16* srch = g_H[L] + (size_t)(t - 1) * BH;
#pragma unroll
            for (int r = 0; r < 8; ++r)
                cp16(ash_s + (hdst + r * 4 * KPAD) * 2, srch + (brow + r * 4) * 512 + kcol);
            cp_commit();
        }

        // ---- x-mma kc 2..3 (hides h load latency) ----
#pragma unroll
        for (int kc = 2; kc < 4; ++kc) {
            int k0 = ks * 64 + kc * 16 + t4 * 2;
#pragma unroll
            for (int nt = 0; nt < 4; ++nt) {
                const __nv_bfloat16* bp = Ash + (nt * 8 + gid) * KPAD + k0;
                uint32_t b0 = *(const uint32_t*)bp;
                uint32_t b1 = *(const uint32_t*)(bp + 8);
                mma16816(acc[0][nt], areg[0][kc][0], b0, b1);
                mma16816(acc[1][nt], areg[0][kc][1], b0, b1);
            }
        }

        // ---- h-half MMA ----
        cp_wait<0>();
        __syncwarp();
#pragma unroll
        for (int kc = 0; kc < 4; ++kc) {
            int k0 = 512 + ks * 64 + kc * 16 + t4 * 2;
#pragma unroll
            for (int nt = 0; nt < 4; ++nt) {
                const __nv_bfloat16* bp = Ash + (nt * 8 + gid) * KPAD + k0;
                uint32_t b0 = *(const uint32_t*)bp;
                uint32_t b1 = *(const uint32_t*)(bp + 8);
                mma16816(acc[0][nt], areg[1][kc][0], b0, b1);
                mma16816(acc[1][nt], areg[1][kc][1], b0, b1);
            }
        }

        // ---- write k-partials ----
#pragma unroll
        for (int mb = 0; mb < 2; ++mb)
#pragma unroll
            for (int nt = 0; nt < 4; ++nt) {
                int r = ks * 32 + mb * 16 + gid;
                int c = nt * 8 + t4 * 2;
                Psum[r * 33 + c]           = acc[mb][nt][0];
                Psum[r * 33 + c + 1]       = acc[mb][nt][1];
                Psum[(r + 8) * 33 + c]     = acc[mb][nt][2];
                Psum[(r + 8) * 33 + c + 1] = acc[mb][nt][3];
            }

        // ---- prefetch x(t+1); latency hides under reduce+publish ----
        if (t < TT) {
            if (L == 1) wait_flags8(fl0, t + 1, lane);
            const __nv_bfloat16* srcx = (L == 0) ? (g_X + (size_t)t * BH)
                                                 : (g_H[0] + (size_t)(t + 1) * BH);
#pragma unroll
            for (int r = 0; r < 8; ++r)
                cp16(ash_s + (xdst + r * 4 * KPAD) * 2, srcx + (brow + r * 4) * 512 + kcol);
            cp_commit();
        }
        __syncthreads();

        // ---- reduce + cell update: thread (b = tid>>3, j = tid&7) ----
        {
            float gv[4];
#pragma unroll
            for (int g = 0; g < 4; ++g) {
                int row = g * 8 + jact;
                float v = bias_r[g];
#pragma unroll
                for (int w = 0; w < 8; ++w) v += Psum[(w * 32 + row) * 33 + bact];
                gv[g] = v;
            }
            float ig = sigmoidf_(gv[0]);
            float fg = sigmoidf_(gv[1]);
            float gg = tanhf(gv[2]);
            float og = sigmoidf_(gv[3]);
            c_reg = fg * c_reg + ig * gg;
            float h_new = og * tanhf(c_reg);
            g_H[L][(size_t)t * BH + bact * 512 + s * 8 + jact] = __float2bfloat16(h_new);
        }
        __syncthreads();   // all h stores done (also protects Psum reuse)

        // ---- publish: one release store, no atomics ----
        if (tid == 0) st_rel(&flags_own[s], t);
    }
}

// ---------------- final FC + sigmoid ----------------------------------------
__global__ void fc_kernel(const float* __restrict__ fc_w,
                          const float* __restrict__ fc_b,
                          float* __restrict__ out) {
    __shared__ float part[512];
    int tid = threadIdx.x;                 // 512 threads: (b, o, p8)
    int p = tid & 7, o = (tid >> 3) & 1, b = tid >> 4;
    const __nv_bfloat16* h = g_H[1] + (size_t)TT * BH + b * 512 + p * 64;
    const float* w = fc_w + o * 512 + p * 64;
    float sum = 0.0f;
#pragma unroll
    for (int u = 0; u < 64; ++u) sum += __bfloat162float(h[u]) * w[u];
    part[tid] = sum;
    __syncthreads();
    if (p == 0) {
        float v = fc_b[o];
#pragma unroll
        for (int q = 0; q < 8; ++q) v += part[tid + q];
        out[b * 2 + o] = sigmoidf_(v);
    }
}

// ---------------- launch -----------------------------------------------------
extern "C" void kernel_launch(void* const* d_in, const int* in_sizes, int n_in,
                              void* d_out, int out_size) {
    const int*   tokens = (const int*)d_in[0];
    const float* emb    = (const float*)d_in[1];
    const float* w_ih   = (const float*)d_in[2];
    const float* w_hh   = (const float*)d_in[3];
    const float* b_ih   = (const float*)d_in[4];
    const float* b_hh   = (const float*)d_in[5];
    const float* fc_w   = (const float*)d_in[6];
    const float* fc_b   = (const float*)d_in[7];
    float* out = (float*)d_out;

    cudaFuncSetAttribute(lstm_kernel, cudaFuncAttributeMaxDynamicSharedMemorySize, SMEM_BYTES);

    prep_w_kernel<<<16384, 256>>>(w_ih, w_hh, b_ih, b_hh);
    gather_x_kernel<<<16384, 256>>>(tokens, emb);
    init_kernel<<<64, 256>>>();
    lstm_kernel<<<NCTA, 256, SMEM_BYTES>>>();
    fc_kernel<<<1, 512>>>(fc_w, fc_b, out);
}

// round 6
// speedup vs baseline: 1.5250x; 1.4245x over previous
#include <cuda_runtime.h>
#include <cuda_bf16.h>
#include <cstdint>

// Problem constants
#define TT    2048
#define BB    32
#define HHID  512
#define KK    1024          // concat input dim [x|h] or [h1|h2]
#define KPAD  1032          // padded K stride in SMEM (conflict-free)
#define NPL   64            // CTAs per layer
#define NCTA  128           // total persistent CTAs
#define BH    (BB*HHID)     // 16384 elements per timestep slice
#define NFLAG ((TT + 1) * 64)

// ---------------- device global scratch -------------------------------------
__device__ __nv_bfloat16 g_X[(size_t)TT * BH];                 // gathered embeddings
__device__ __nv_bfloat16 g_H[2][(size_t)(TT + 1) * BH];        // h per layer per step
__device__ __nv_bfloat16 g_W[(size_t)NCTA * 32 * KK];          // per-CTA weight slices
__device__ float         g_bias[NCTA * 32];
__device__ int           g_flag[2][NFLAG];                     // [L][t*64+s], write-once per address

// ---------------- helpers ---------------------------------------------------
__device__ __forceinline__ void mma16816(float* c, const uint32_t* a,
                                         uint32_t b0, uint32_t b1) {
    asm volatile(
        "mma.sync.aligned.m16n8k16.row.col.f32.bf16.bf16.f32 "
        "{%0,%1,%2,%3},{%4,%5,%6,%7},{%8,%9},{%0,%1,%2,%3};\n"
        : "+f"(c[0]), "+f"(c[1]), "+f"(c[2]), "+f"(c[3])
        : "r"(a[0]), "r"(a[1]), "r"(a[2]), "r"(a[3]), "r"(b0), "r"(b1));
}

__device__ __forceinline__ float sigmoidf_(float x) {
    return 1.0f / (1.0f + __expf(-x));
}

__device__ __forceinline__ int ld_acq(const int* p) {
    int v;
    asm volatile("ld.acquire.gpu.global.s32 %0, [%1];" : "=r"(v) : "l"(p) : "memory");
    return v;
}
__device__ __forceinline__ void st_rel(int* p, int v) {
    asm volatile("st.release.gpu.global.s32 [%0], %1;" :: "l"(p), "r"(v) : "memory");
}
// warp-collective wait: 8 write-once flags (one 32B sector), lanes 0..7 poll, throttled
__device__ __forceinline__ void wait_flags8(const int* p, int lane) {
    int v = 1;
    if (lane < 8) v = ld_acq(p + lane);
    while (__any_sync(0xffffffffu, v == 0)) {
        __nanosleep(32);
        if (lane < 8) v = ld_acq(p + lane);
    }
    __syncwarp();
}
__device__ __forceinline__ void cp16(uint32_t dst_smem, const void* src) {
    asm volatile("cp.async.cg.shared.global [%0], [%1], 16;\n" :: "r"(dst_smem), "l"(src));
}
__device__ __forceinline__ void cp_commit() {
    asm volatile("cp.async.commit_group;\n" ::: "memory");
}
template<int N>
__device__ __forceinline__ void cp_wait() {
    asm volatile("cp.async.wait_group %0;\n" :: "n"(N) : "memory");
}

// ---------------- prep: reorganize weights to per-CTA bf16 slices -----------
__global__ void prep_w_kernel(const float* __restrict__ w_ih,
                              const float* __restrict__ w_hh,
                              const float* __restrict__ b_ih,
                              const float* __restrict__ b_hh) {
    int idx = blockIdx.x * blockDim.x + threadIdx.x;
    if (idx >= NCTA * 32 * KK) return;
    int k   = idx & 1023;
    int r   = (idx >> 10) & 31;
    int cta = idx >> 15;
    int L = cta >> 6, s = cta & 63;
    int g = r >> 3,  j = r & 7;
    int col = g * 512 + s * 8 + j;
    size_t base = ((size_t)L * 2048 + col) * 512;
    float w = (k < 512) ? w_ih[base + k] : w_hh[base + (k - 512)];
    g_W[idx] = __float2bfloat16(w);
    if (k == 0) g_bias[cta * 32 + r] = b_ih[L * 2048 + col] + b_hh[L * 2048 + col];
}

// ---------------- prep: embedding gather to bf16 [t][b][k] ------------------
__global__ void gather_x_kernel(const int* __restrict__ tokens,
                                const float* __restrict__ emb) {
    int idx = blockIdx.x * blockDim.x + threadIdx.x;
    if (idx >= TT * BB * 64) return;
    int k8 = idx & 63;
    int b  = (idx >> 6) & 31;
    int t  = idx >> 11;
    int tok = tokens[b * TT + t];
    const float* e = emb + (size_t)tok * 512 + k8 * 8;
    __nv_bfloat16 v[8];
#pragma unroll
    for (int i = 0; i < 8; ++i) v[i] = __float2bfloat16(e[i]);
    *(uint4*)(g_X + ((size_t)t * BB + b) * 512 + k8 * 8) = *(uint4*)v;
}

// ---------------- prep: init state ------------------------------------------
__global__ void init_kernel() {
    int idx = blockIdx.x * blockDim.x + threadIdx.x;
    if (idx < BH) {
        __nv_bfloat16 z = __float2bfloat16(0.0f);
        g_H[0][idx] = z;
        g_H[1][idx] = z;
    }
    if (idx < 2 * NFLAG) {
        // flag layout: L*NFLAG + t*64 + s ; pre-satisfy t==0
        int within = idx % NFLAG;
        ((int*)g_flag)[idx] = (within < 64) ? 1 : 0;
    }
}

// ---------------- the persistent LSTM kernel --------------------------------
// 128 CTAs (64/layer), 256 threads. Weights in registers.
// Sync: write-once rotating flags g_flag[L][t*64+s]; consumer warp ks waits on
// exactly its 8 producers (one 32B sector, fresh addresses every step).
#define SMEM_ACT_BYTES (32 * KPAD * 2)
#define SMEM_BYTES     (SMEM_ACT_BYTES + 8 * 32 * 33 * 4)

__global__ void __launch_bounds__(256, 1) lstm_kernel() {
    extern __shared__ unsigned char smem_raw[];
    __nv_bfloat16* Ash  = (__nv_bfloat16*)smem_raw;
    float*         Psum = (float*)(smem_raw + SMEM_ACT_BYTES);
    uint32_t ash_s = (uint32_t)__cvta_generic_to_shared(Ash);

    const int tid = threadIdx.x;
    const int cta = blockIdx.x;
    const int L = cta >> 6;
    const int s = cta & 63;

    const int ks   = tid >> 5;          // warp = k-slice
    const int lane = tid & 31;
    const int gid  = lane >> 2;
    const int t4   = lane & 3;

    // ---- load weight fragments into registers (once) ----
    const __nv_bfloat16* wsrc = g_W + (size_t)cta * 32 * KK;
    uint32_t areg[2][4][2][4];          // [half][kc][mb][frag]
#pragma unroll
    for (int half = 0; half < 2; ++half)
#pragma unroll
        for (int kc = 0; kc < 4; ++kc) {
            int k0 = half * 512 + ks * 64 + kc * 16 + t4 * 2;
#pragma unroll
            for (int mb = 0; mb < 2; ++mb) {
                int r = mb * 16 + gid;
                areg[half][kc][mb][0] = *(const uint32_t*)(wsrc + r * KK + k0);
                areg[half][kc][mb][1] = *(const uint32_t*)(wsrc + (r + 8) * KK + k0);
                areg[half][kc][mb][2] = *(const uint32_t*)(wsrc + r * KK + k0 + 8);
                areg[half][kc][mb][3] = *(const uint32_t*)(wsrc + (r + 8) * KK + k0 + 8);
            }
        }

    // ---- bias + cell state in registers ----
    const int bact = tid >> 3, jact = tid & 7;      // tid = b*8 + j
    float bias_r[4];
#pragma unroll
    for (int g = 0; g < 4; ++g) bias_r[g] = g_bias[cta * 32 + g * 8 + jact];
    float c_reg = 0.0f;

    int* flags_own = &g_flag[L][0];
    int* flags_l0  = &g_flag[0][0];

    // per-warp cp.async lane mapping
    const int c8   = lane & 7;
    const int brow = lane >> 3;
    const int kcol = ks * 64 + c8 * 8;
    const int xdst = (brow * KPAD + kcol);
    const int hdst = (brow * KPAD + 512 + kcol);

    // ---- prologue: prefetch x(1) ----
    if (L == 1) wait_flags8(flags_l0 + 1 * 64 + ks * 8, lane);
    {
        const __nv_bfloat16* srcx = (L == 0) ? g_X : (g_H[0] + (size_t)BH);
#pragma unroll
        for (int r = 0; r < 8; ++r)
            cp16(ash_s + (xdst + r * 4 * KPAD) * 2, srcx + (brow + r * 4) * 512 + kcol);
        cp_commit();
    }

    for (int t = 1; t <= TT; ++t) {
        float acc[2][4][4];
#pragma unroll
        for (int mb = 0; mb < 2; ++mb)
#pragma unroll
            for (int nt = 0; nt < 4; ++nt)
#pragma unroll
                for (int i = 0; i < 4; ++i) acc[mb][nt][i] = 0.0f;

        // ---- x(t) ready (prefetched) ----
        cp_wait<0>();
        __syncwarp();

        // ---- x-mma kc 0..1 (overlaps producers' publish propagation) ----
#pragma unroll
        for (int kc = 0; kc < 2; ++kc) {
            int k0 = ks * 64 + kc * 16 + t4 * 2;
#pragma unroll
            for (int nt = 0; nt < 4; ++nt) {
                const __nv_bfloat16* bp = Ash + (nt * 8 + gid) * KPAD + k0;
                uint32_t b0 = *(const uint32_t*)bp;
                uint32_t b1 = *(const uint32_t*)(bp + 8);
                mma16816(acc[0][nt], areg[0][kc][0], b0, b1);
                mma16816(acc[1][nt], areg[0][kc][1], b0, b1);
            }
        }

        // ---- wait own-layer h(t-1) producers (8 rotating flags), issue h ----
        wait_flags8(flags_own + (t - 1) * 64 + ks * 8, lane);
        {
            const __nv_bfloat16* srch = g_H[L] + (size_t)(t - 1) * BH;
#pragma unroll
            for (int r = 0; r < 8; ++r)
                cp16(ash_s + (hdst + r * 4 * KPAD) * 2, srch + (brow + r * 4) * 512 + kcol);
            cp_commit();
        }

        // ---- x-mma kc 2..3 (hides h load latency) ----
#pragma unroll
        for (int kc = 2; kc < 4; ++kc) {
            int k0 = ks * 64 + kc * 16 + t4 * 2;
#pragma unroll
            for (int nt = 0; nt < 4; ++nt) {
                const __nv_bfloat16* bp = Ash + (nt * 8 + gid) * KPAD + k0;
                uint32_t b0 = *(const uint32_t*)bp;
                uint32_t b1 = *(const uint32_t*)(bp + 8);
                mma16816(acc[0][nt], areg[0][kc][0], b0, b1);
                mma16816(acc[1][nt], areg[0][kc][1], b0, b1);
            }
        }

        // ---- h-half MMA ----
        cp_wait<0>();
        __syncwarp();
#pragma unroll
        for (int kc = 0; kc < 4; ++kc) {
            int k0 = 512 + ks * 64 + kc * 16 + t4 * 2;
#pragma unroll
            for (int nt = 0; nt < 4; ++nt) {
                const __nv_bfloat16* bp = Ash + (nt * 8 + gid) * KPAD + k0;
                uint32_t b0 = *(const uint32_t*)bp;
                uint32_t b1 = *(const uint32_t*)(bp + 8);
                mma16816(acc[0][nt], areg[1][kc][0], b0, b1);
                mma16816(acc[1][nt], areg[1][kc][1], b0, b1);
            }
        }

        // ---- write k-partials ----
#pragma unroll
        for (int mb = 0; mb < 2; ++mb)
#pragma unroll
            for (int nt = 0; nt < 4; ++nt) {
                int r = ks * 32 + mb * 16 + gid;
                int c = nt * 8 + t4 * 2;
                Psum[r * 33 + c]           = acc[mb][nt][0];
                Psum[r * 33 + c + 1]       = acc[mb][nt][1];
                Psum[(r + 8) * 33 + c]     = acc[mb][nt][2];
                Psum[(r + 8) * 33 + c + 1] = acc[mb][nt][3];
            }
        __syncthreads();

        // ---- reduce + cell update: thread (b = tid>>3, j = tid&7) ----
        {
            float gv[4];
#pragma unroll
            for (int g = 0; g < 4; ++g) {
                int row = g * 8 + jact;
                float v = bias_r[g];
#pragma unroll
                for (int w = 0; w < 8; ++w) v += Psum[(w * 32 + row) * 33 + bact];
                gv[g] = v;
            }
            float ig = sigmoidf_(gv[0]);
            float fg = sigmoidf_(gv[1]);
            float gg = tanhf(gv[2]);
            float og = sigmoidf_(gv[3]);
            c_reg = fg * c_reg + ig * gg;
            float h_new = og * tanhf(c_reg);
            g_H[L][(size_t)t * BH + bact * 512 + s * 8 + jact] = __float2bfloat16(h_new);
        }
        __syncthreads();   // all h stores done (also protects Psum reuse)

        // ---- publish: one release store to a fresh (write-once) address ----
        if (tid == 0) st_rel(&flags_own[t * 64 + s], 1);

        // ---- prefetch x(t+1) AFTER publish (never delays own publication) ----
        if (t < TT) {
            if (L == 1) wait_flags8(flags_l0 + (t + 1) * 64 + ks * 8, lane);
            const __nv_bfloat16* srcx = (L == 0) ? (g_X + (size_t)t * BH)
                                                 : (g_H[0] + (size_t)(t + 1) * BH);
#pragma unroll
            for (int r = 0; r < 8; ++r)
                cp16(ash_s + (xdst + r * 4 * KPAD) * 2, srcx + (brow + r * 4) * 512 + kcol);
            cp_commit();
        }
    }
}

// ---------------- final FC + sigmoid ----------------------------------------
__global__ void fc_kernel(const float* __restrict__ fc_w,
                          const float* __restrict__ fc_b,
                          float* __restrict__ out) {
    __shared__ float part[512];
    int tid = threadIdx.x;                 // 512 threads: (b, o, p8)
    int p = tid & 7, o = (tid >> 3) & 1, b = tid >> 4;
    const __nv_bfloat16* h = g_H[1] + (size_t)TT * BH + b * 512 + p * 64;
    const float* w = fc_w + o * 512 + p * 64;
    float sum = 0.0f;
#pragma unroll
    for (int u = 0; u < 64; ++u) sum += __bfloat162float(h[u]) * w[u];
    part[tid] = sum;
    __syncthreads();
    if (p == 0) {
        float v = fc_b[o];
#pragma unroll
        for (int q = 0; q < 8; ++q) v += part[tid + q];
        out[b * 2 + o] = sigmoidf_(v);
    }
}

// ---------------- launch -----------------------------------------------------
extern "C" void kernel_launch(void* const* d_in, const int* in_sizes, int n_in,
                              void* d_out, int out_size) {
    const int*   tokens = (const int*)d_in[0];
    const float* emb    = (const float*)d_in[1];
    const float* w_ih   = (const float*)d_in[2];
    const float* w_hh   = (const float*)d_in[3];
    const float* b_ih   = (const float*)d_in[4];
    const float* b_hh   = (const float*)d_in[5];
    const float* fc_w   = (const float*)d_in[6];
    const float* fc_b   = (const float*)d_in[7];
    float* out = (float*)d_out;

    cudaFuncSetAttribute(lstm_kernel, cudaFuncAttributeMaxDynamicSharedMemorySize, SMEM_BYTES);

    prep_w_kernel<<<16384, 256>>>(w_ih, w_hh, b_ih, b_hh);
    gather_x_kernel<<<16384, 256>>>(tokens, emb);
    init_kernel<<<1026, 256>>>();
    lstm_kernel<<<NCTA, 256, SMEM_BYTES>>>();
    fc_kernel<<<1, 512>>>(fc_w, fc_b, out);
}

// round 7
// speedup vs baseline: 1.8701x; 1.2263x over previous
#include <cuda_runtime.h>
#include <cuda_bf16.h>
#include <cstdint>

// Problem constants
#define TT    2048
#define BB    32
#define HHID  512
#define KK    1024          // concat input dim [x|h] or [h1|h2]
#define KPAD  1032          // padded K stride in SMEM (conflict-free)
#define NPL   64            // CTAs per layer
#define NCTA  128           // total persistent CTAs
#define BH    (BB*HHID)     // 16384 elements per timestep slice
#define FL    ((TT + 1) * 64 * 8)      // padded flags per layer (32B sector each)

// ---------------- device global scratch -------------------------------------
__device__ __nv_bfloat16 g_X[(size_t)TT * BH];                 // gathered embeddings
__device__ __nv_bfloat16 g_H[2][(size_t)(TT + 1) * BH];        // h per layer per step
__device__ __nv_bfloat16 g_W[(size_t)NCTA * 32 * KK];          // per-CTA weight slices
__device__ float         g_bias[NCTA * 32];
__device__ int           g_flagP[2 * FL];                      // write-once, 32B-padded flags

// ---------------- helpers ---------------------------------------------------
__device__ __forceinline__ void mma16816(float* c, const uint32_t* a,
                                         uint32_t b0, uint32_t b1) {
    asm volatile(
        "mma.sync.aligned.m16n8k16.row.col.f32.bf16.bf16.f32 "
        "{%0,%1,%2,%3},{%4,%5,%6,%7},{%8,%9},{%0,%1,%2,%3};\n"
        : "+f"(c[0]), "+f"(c[1]), "+f"(c[2]), "+f"(c[3])
        : "r"(a[0]), "r"(a[1]), "r"(a[2]), "r"(a[3]), "r"(b0), "r"(b1));
}

__device__ __forceinline__ float sigmoidf_(float x) {
    return 1.0f / (1.0f + __expf(-x));
}

__device__ __forceinline__ int ld_acq(const int* p) {
    int v;
    asm volatile("ld.acquire.gpu.global.s32 %0, [%1];" : "=r"(v) : "l"(p) : "memory");
    return v;
}
__device__ __forceinline__ void st_rel(int* p, int v) {
    asm volatile("st.release.gpu.global.s32 [%0], %1;" :: "l"(p), "r"(v) : "memory");
}
// warp0-only: poll all 64 padded flags of one (L, t) group. Lane l covers
// flags s=l and s=l+32 (each its own 32B sector).
__device__ __forceinline__ void poll64(const int* base, int lane) {
    const int* p0 = base + lane * 8;
    const int* p1 = base + (lane + 32) * 8;
    int a = ld_acq(p0);
    int b = ld_acq(p1);
    while (__any_sync(0xffffffffu, (a == 0) | (b == 0))) {
        __nanosleep(64);
        if (a == 0) a = ld_acq(p0);
        if (b == 0) b = ld_acq(p1);
    }
    __syncwarp();
}
__device__ __forceinline__ void cp16(uint32_t dst_smem, const void* src) {
    asm volatile("cp.async.cg.shared.global [%0], [%1], 16;\n" :: "r"(dst_smem), "l"(src));
}
__device__ __forceinline__ void cp_commit() {
    asm volatile("cp.async.commit_group;\n" ::: "memory");
}
template<int N>
__device__ __forceinline__ void cp_wait() {
    asm volatile("cp.async.wait_group %0;\n" :: "n"(N) : "memory");
}

// ---------------- prep: reorganize weights to per-CTA bf16 slices -----------
__global__ void prep_w_kernel(const float* __restrict__ w_ih,
                              const float* __restrict__ w_hh,
                              const float* __restrict__ b_ih,
                              const float* __restrict__ b_hh) {
    int idx = blockIdx.x * blockDim.x + threadIdx.x;
    if (idx >= NCTA * 32 * KK) return;
    int k   = idx & 1023;
    int r   = (idx >> 10) & 31;
    int cta = idx >> 15;
    int L = cta >> 6, s = cta & 63;
    int g = r >> 3,  j = r & 7;
    int col = g * 512 + s * 8 + j;
    size_t base = ((size_t)L * 2048 + col) * 512;
    float w = (k < 512) ? w_ih[base + k] : w_hh[base + (k - 512)];
    g_W[idx] = __float2bfloat16(w);
    if (k == 0) g_bias[cta * 32 + r] = b_ih[L * 2048 + col] + b_hh[L * 2048 + col];
}

// ---------------- prep: embedding gather to bf16 [t][b][k] ------------------
__global__ void gather_x_kernel(const int* __restrict__ tokens,
                                const float* __restrict__ emb) {
    int idx = blockIdx.x * blockDim.x + threadIdx.x;
    if (idx >= TT * BB * 64) return;
    int k8 = idx & 63;
    int b  = (idx >> 6) & 31;
    int t  = idx >> 11;
    int tok = tokens[b * TT + t];
    const float* e = emb + (size_t)tok * 512 + k8 * 8;
    __nv_bfloat16 v[8];
#pragma unroll
    for (int i = 0; i < 8; ++i) v[i] = __float2bfloat16(e[i]);
    *(uint4*)(g_X + ((size_t)t * BB + b) * 512 + k8 * 8) = *(uint4*)v;
}

// ---------------- prep: init (zero flags + h0 + pre-satisfy t=0) ------------
__global__ void init_kernel() {
    int idx = blockIdx.x * blockDim.x + threadIdx.x;
    // zero all flags via 16B stores: 2*FL ints / 4 per store
    int n16 = 2 * FL / 4;
    if (idx < n16) {
        uint4 z = {0, 0, 0, 0};
        *(uint4*)(g_flagP + idx * 4) = z;
    }
    if (idx < BH) {
        __nv_bfloat16 z = __float2bfloat16(0.0f);
        g_H[0][idx] = z;
        g_H[1][idx] = z;
    }
}
__global__ void init_flags_kernel() {
    int idx = threadIdx.x;                 // 128 threads: (L, s)
    int L = idx >> 6, s = idx & 63;
    g_flagP[L * FL + s * 8] = 1;           // pre-satisfy t=0
}

// ---------------- the persistent LSTM kernel --------------------------------
// 128 CTAs (64/layer), 256 threads. Weights in registers.
// Sync: write-once, 32B-padded, rotating flags. ONE poller warp (warp 0) per
// CTA; other warps overlap MMA with the poll; barrier broadcast.
#define SMEM_ACT_BYTES (32 * KPAD * 2)
#define SMEM_BYTES     (SMEM_ACT_BYTES + 8 * 32 * 33 * 4)

__global__ void __launch_bounds__(256, 1) lstm_kernel() {
    extern __shared__ unsigned char smem_raw[];
    __nv_bfloat16* Ash  = (__nv_bfloat16*)smem_raw;
    float*         Psum = (float*)(smem_raw + SMEM_ACT_BYTES);
    uint32_t ash_s = (uint32_t)__cvta_generic_to_shared(Ash);

    const int tid = threadIdx.x;
    const int cta = blockIdx.x;
    const int L = cta >> 6;
    const int s = cta & 63;

    const int ks   = tid >> 5;          // warp = k-slice
    const int lane = tid & 31;
    const int gid  = lane >> 2;
    const int t4   = lane & 3;

    // ---- load weight fragments into registers (once) ----
    const __nv_bfloat16* wsrc = g_W + (size_t)cta * 32 * KK;
    uint32_t areg[2][4][2][4];          // [half][kc][mb][frag]
#pragma unroll
    for (int half = 0; half < 2; ++half)
#pragma unroll
        for (int kc = 0; kc < 4; ++kc) {
            int k0 = half * 512 + ks * 64 + kc * 16 + t4 * 2;
#pragma unroll
            for (int mb = 0; mb < 2; ++mb) {
                int r = mb * 16 + gid;
                areg[half][kc][mb][0] = *(const uint32_t*)(wsrc + r * KK + k0);
                areg[half][kc][mb][1] = *(const uint32_t*)(wsrc + (r + 8) * KK + k0);
                areg[half][kc][mb][2] = *(const uint32_t*)(wsrc + r * KK + k0 + 8);
                areg[half][kc][mb][3] = *(const uint32_t*)(wsrc + (r + 8) * KK + k0 + 8);
            }
        }

    // ---- bias + cell state in registers ----
    const int bact = tid >> 3, jact = tid & 7;      // tid = b*8 + j
    float bias_r[4];
#pragma unroll
    for (int g = 0; g < 4; ++g) bias_r[g] = g_bias[cta * 32 + g * 8 + jact];
    float c_reg = 0.0f;

    int* flags_own = g_flagP + L * FL;
    int* flags_l0  = g_flagP;

    // per-warp cp.async lane mapping
    const int c8   = lane & 7;
    const int brow = lane >> 3;
    const int kcol = ks * 64 + c8 * 8;
    const int xdst = (brow * KPAD + kcol);
    const int hdst = (brow * KPAD + 512 + kcol);

    // ---- prologue: prefetch x(1) ----
    if (L == 1) {
        if (ks == 0) poll64(flags_l0 + 1 * 64 * 8, lane);
        __syncthreads();
    }
    {
        const __nv_bfloat16* srcx = (L == 0) ? g_X : (g_H[0] + (size_t)BH);
#pragma unroll
        for (int r = 0; r < 8; ++r)
            cp16(ash_s + (xdst + r * 4 * KPAD) * 2, srcx + (brow + r * 4) * 512 + kcol);
        cp_commit();
    }

    for (int t = 1; t <= TT; ++t) {
        float acc[2][4][4];
#pragma unroll
        for (int mb = 0; mb < 2; ++mb)
#pragma unroll
            for (int nt = 0; nt < 4; ++nt)
#pragma unroll
                for (int i = 0; i < 4; ++i) acc[mb][nt][i] = 0.0f;

        // ---- x(t) ready (prefetched) ----
        cp_wait<0>();
        __syncwarp();

        // ---- x-mma kc 0..1 (all warps) ----
#pragma unroll
        for (int kc = 0; kc < 2; ++kc) {
            int k0 = ks * 64 + kc * 16 + t4 * 2;
#pragma unroll
            for (int nt = 0; nt < 4; ++nt) {
                const __nv_bfloat16* bp = Ash + (nt * 8 + gid) * KPAD + k0;
                uint32_t b0 = *(const uint32_t*)bp;
                uint32_t b1 = *(const uint32_t*)(bp + 8);
                mma16816(acc[0][nt], areg[0][kc][0], b0, b1);
                mma16816(acc[1][nt], areg[0][kc][1], b0, b1);
            }
        }

        // ---- warp0 polls h(t-1) flags; warps 1..7 finish x-mma meanwhile ----
        if (ks == 0) {
            poll64(flags_own + (t - 1) * 64 * 8, lane);
        } else {
#pragma unroll
            for (int kc = 2; kc < 4; ++kc) {
                int k0 = ks * 64 + kc * 16 + t4 * 2;
#pragma unroll
                for (int nt = 0; nt < 4; ++nt) {
                    const __nv_bfloat16* bp = Ash + (nt * 8 + gid) * KPAD + k0;
                    uint32_t b0 = *(const uint32_t*)bp;
                    uint32_t b1 = *(const uint32_t*)(bp + 8);
                    mma16816(acc[0][nt], areg[0][kc][0], b0, b1);
                    mma16816(acc[1][nt], areg[0][kc][1], b0, b1);
                }
            }
        }
        __syncthreads();        // h(t-1) now visible to whole CTA

        // ---- all warps issue their h slice loads ----
        {
            const __nv_bfloat16* srch = g_H[L] + (size_t)(t - 1) * BH;
#pragma unroll
            for (int r = 0; r < 8; ++r)
                cp16(ash_s + (hdst + r * 4 * KPAD) * 2, srch + (brow + r * 4) * 512 + kcol);
            cp_commit();
        }

        // ---- warp0 finishes its x-mma (hides its h-load latency) ----
        if (ks == 0) {
#pragma unroll
            for (int kc = 2; kc < 4; ++kc) {
                int k0 = ks * 64 + kc * 16 + t4 * 2;
#pragma unroll
                for (int nt = 0; nt < 4; ++nt) {
                    const __nv_bfloat16* bp = Ash + (nt * 8 + gid) * KPAD + k0;
                    uint32_t b0 = *(const uint32_t*)bp;
                    uint32_t b1 = *(const uint32_t*)(bp + 8);
                    mma16816(acc[0][nt], areg[0][kc][0], b0, b1);
                    mma16816(acc[1][nt], areg[0][kc][1], b0, b1);
                }
            }
        }

        // ---- h-half MMA ----
        cp_wait<0>();
        __syncwarp();
#pragma unroll
        for (int kc = 0; kc < 4; ++kc) {
            int k0 = 512 + ks * 64 + kc * 16 + t4 * 2;
#pragma unroll
            for (int nt = 0; nt < 4; ++nt) {
                const __nv_bfloat16* bp = Ash + (nt * 8 + gid) * KPAD + k0;
                uint32_t b0 = *(const uint32_t*)bp;
                uint32_t b1 = *(const uint32_t*)(bp + 8);
                mma16816(acc[0][nt], areg[1][kc][0], b0, b1);
                mma16816(acc[1][nt], areg[1][kc][1], b0, b1);
            }
        }

        // ---- write k-partials ----
#pragma unroll
        for (int mb = 0; mb < 2; ++mb)
#pragma unroll
            for (int nt = 0; nt < 4; ++nt) {
                int r = ks * 32 + mb * 16 + gid;
                int c = nt * 8 + t4 * 2;
                Psum[r * 33 + c]           = acc[mb][nt][0];
                Psum[r * 33 + c + 1]       = acc[mb][nt][1];
                Psum[(r + 8) * 33 + c]     = acc[mb][nt][2];
                Psum[(r + 8) * 33 + c + 1] = acc[mb][nt][3];
            }
        __syncthreads();

        // ---- reduce + cell update: thread (b = tid>>3, j = tid&7) ----
        {
            float gv[4];
#pragma unroll
            for (int g = 0; g < 4; ++g) {
                int row = g * 8 + jact;
                float v = bias_r[g];
#pragma unroll
                for (int w = 0; w < 8; ++w) v += Psum[(w * 32 + row) * 33 + bact];
                gv[g] = v;
            }
            float ig = sigmoidf_(gv[0]);
            float fg = sigmoidf_(gv[1]);
            float gg = tanhf(gv[2]);
            float og = sigmoidf_(gv[3]);
            c_reg = fg * c_reg + ig * gg;
            float h_new = og * tanhf(c_reg);
            g_H[L][(size_t)t * BH + bact * 512 + s * 8 + jact] = __float2bfloat16(h_new);
        }
        __syncthreads();   // all h stores done (also protects Psum reuse)

        // ---- publish: one release store, own 32B sector, write-once ----
        if (tid == 0) st_rel(&flags_own[(t * 64 + s) * 8], 1);

        // ---- prefetch x(t+1) AFTER publish ----
        if (t < TT) {
            if (L == 1) {
                if (ks == 0) poll64(flags_l0 + (t + 1) * 64 * 8, lane);
                __syncthreads();
            }
            const __nv_bfloat16* srcx = (L == 0) ? (g_X + (size_t)t * BH)
                                                 : (g_H[0] + (size_t)(t + 1) * BH);
#pragma unroll
            for (int r = 0; r < 8; ++r)
                cp16(ash_s + (xdst + r * 4 * KPAD) * 2, srcx + (brow + r * 4) * 512 + kcol);
            cp_commit();
        }
    }
}

// ---------------- final FC + sigmoid ----------------------------------------
__global__ void fc_kernel(const float* __restrict__ fc_w,
                          const float* __restrict__ fc_b,
                          float* __restrict__ out) {
    __shared__ float part[512];
    int tid = threadIdx.x;                 // 512 threads: (b, o, p8)
    int p = tid & 7, o = (tid >> 3) & 1, b = tid >> 4;
    const __nv_bfloat16* h = g_H[1] + (size_t)TT * BH + b * 512 + p * 64;
    const float* w = fc_w + o * 512 + p * 64;
    float sum = 0.0f;
#pragma unroll
    for (int u = 0; u < 64; ++u) sum += __bfloat162float(h[u]) * w[u];
    part[tid] = sum;
    __syncthreads();
    if (p == 0) {
        float v = fc_b[o];
#pragma unroll
        for (int q = 0; q < 8; ++q) v += part[tid + q];
        out[b * 2 + o] = sigmoidf_(v);
    }
}

// ---------------- launch -----------------------------------------------------
extern "C" void kernel_launch(void* const* d_in, const int* in_sizes, int n_in,
                              void* d_out, int out_size) {
    const int*   tokens = (const int*)d_in[0];
    const float* emb    = (const float*)d_in[1];
    const float* w_ih   = (const float*)d_in[2];
    const float* w_hh   = (const float*)d_in[3];
    const float* b_ih   = (const float*)d_in[4];
    const float* b_hh   = (const float*)d_in[5];
    const float* fc_w   = (const float*)d_in[6];
    const float* fc_b   = (const float*)d_in[7];
    float* out = (float*)d_out;

    cudaFuncSetAttribute(lstm_kernel, cudaFuncAttributeMaxDynamicSharedMemorySize, SMEM_BYTES);

    prep_w_kernel<<<16384, 256>>>(w_ih, w_hh, b_ih, b_hh);
    gather_x_kernel<<<16384, 256>>>(tokens, emb);
    init_kernel<<<(2 * FL / 4 + 255) / 256, 256>>>();
    init_flags_kernel<<<1, 128>>>();
    lstm_kernel<<<NCTA, 256, SMEM_BYTES>>>();
    fc_kernel<<<1, 512>>>(fc_w, fc_b, out);
}

// round 8
// speedup vs baseline: 2.5508x; 1.3640x over previous
#include <cuda_runtime.h>
#include <cuda_bf16.h>
#include <cstdint>

// Problem constants
#define TT    2048
#define BB    32
#define HHID  512
#define KK    1024          // concat input dim [x|h] or [h1|h2]
#define KPAD  1032          // padded K stride in SMEM (conflict-free)
#define NPL   64            // CTAs per layer
#define NCTA  128           // total persistent CTAs
#define BH    (BB*HHID)     // 16384 elements per timestep slice
// counters: [L][t][g], g = k-group 0..7, each padded to its own 32B sector
#define CNT_STRIDE 8
#define CNT_PER_L  ((TT + 1) * 8 * CNT_STRIDE)

// ---------------- device global scratch -------------------------------------
__device__ __nv_bfloat16 g_X[(size_t)TT * BH];                 // gathered embeddings
__device__ __nv_bfloat16 g_H[2][(size_t)(TT + 1) * BH];        // h per layer per step
__device__ __nv_bfloat16 g_W[(size_t)NCTA * 32 * KK];          // per-CTA weight slices
__device__ float         g_bias[NCTA * 32];
__device__ int           g_cnt2[2 * CNT_PER_L];                // split counters

// ---------------- helpers ---------------------------------------------------
__device__ __forceinline__ void mma16816(float* c, const uint32_t* a,
                                         uint32_t b0, uint32_t b1) {
    asm volatile(
        "mma.sync.aligned.m16n8k16.row.col.f32.bf16.bf16.f32 "
        "{%0,%1,%2,%3},{%4,%5,%6,%7},{%8,%9},{%0,%1,%2,%3};\n"
        : "+f"(c[0]), "+f"(c[1]), "+f"(c[2]), "+f"(c[3])
        : "r"(a[0]), "r"(a[1]), "r"(a[2]), "r"(a[3]), "r"(b0), "r"(b1));
}

__device__ __forceinline__ float tanh_fast(float x) {
    float y;
    asm("tanh.approx.f32 %0, %1;" : "=f"(y) : "f"(x));
    return y;
}
__device__ __forceinline__ float sig_fast(float x) {
    return fmaf(tanh_fast(0.5f * x), 0.5f, 0.5f);
}

__device__ __forceinline__ int ld_acq(const int* p) {
    int v;
    asm volatile("ld.acquire.gpu.global.s32 %0, [%1];" : "=r"(v) : "l"(p) : "memory");
    return v;
}
__device__ __forceinline__ void red_rel(int* p) {
    asm volatile("red.release.gpu.global.add.s32 [%0], 1;" :: "l"(p) : "memory");
}
// warp-collective wait on ONE split counter (8 producers): lane0 polls
__device__ __forceinline__ void wait_cnt8(const int* p, int lane) {
    int v = 0;
    if (lane == 0) v = ld_acq(p);
    v = __shfl_sync(0xffffffffu, v, 0);
    while (v < 8) {
        __nanosleep(32);
        if (lane == 0) v = ld_acq(p);
        v = __shfl_sync(0xffffffffu, v, 0);
    }
}
__device__ __forceinline__ void cp16(uint32_t dst_smem, const void* src) {
    asm volatile("cp.async.cg.shared.global [%0], [%1], 16;\n" :: "r"(dst_smem), "l"(src));
}
__device__ __forceinline__ void cp_commit() {
    asm volatile("cp.async.commit_group;\n" ::: "memory");
}
template<int N>
__device__ __forceinline__ void cp_wait() {
    asm volatile("cp.async.wait_group %0;\n" :: "n"(N) : "memory");
}

// ---------------- prep: reorganize weights to per-CTA bf16 slices -----------
__global__ void prep_w_kernel(const float* __restrict__ w_ih,
                              const float* __restrict__ w_hh,
                              const float* __restrict__ b_ih,
                              const float* __restrict__ b_hh) {
    int idx = blockIdx.x * blockDim.x + threadIdx.x;
    if (idx >= NCTA * 32 * KK) return;
    int k   = idx & 1023;
    int r   = (idx >> 10) & 31;
    int cta = idx >> 15;
    int L = cta >> 6, s = cta & 63;
    int g = r >> 3,  j = r & 7;
    int col = g * 512 + s * 8 + j;
    size_t base = ((size_t)L * 2048 + col) * 512;
    float w = (k < 512) ? w_ih[base + k] : w_hh[base + (k - 512)];
    g_W[idx] = __float2bfloat16(w);
    if (k == 0) g_bias[cta * 32 + r] = b_ih[L * 2048 + col] + b_hh[L * 2048 + col];
}

// ---------------- prep: embedding gather to bf16 [t][b][k] ------------------
__global__ void gather_x_kernel(const int* __restrict__ tokens,
                                const float* __restrict__ emb) {
    int idx = blockIdx.x * blockDim.x + threadIdx.x;
    if (idx >= TT * BB * 64) return;
    int k8 = idx & 63;
    int b  = (idx >> 6) & 31;
    int t  = idx >> 11;
    int tok = tokens[b * TT + t];
    const float* e = emb + (size_t)tok * 512 + k8 * 8;
    __nv_bfloat16 v[8];
#pragma unroll
    for (int i = 0; i < 8; ++i) v[i] = __float2bfloat16(e[i]);
    *(uint4*)(g_X + ((size_t)t * BB + b) * 512 + k8 * 8) = *(uint4*)v;
}

// ---------------- prep: init state ------------------------------------------
__global__ void init_kernel() {
    int idx = blockIdx.x * blockDim.x + threadIdx.x;
    if (idx < 2 * CNT_PER_L) {
        // pre-satisfy t==0 groups: layout ((L*(TT+1)+t)*8+g)*CNT_STRIDE
        int wl = idx % CNT_PER_L;              // within layer
        g_cnt2[idx] = (wl < 8 * CNT_STRIDE && (wl % CNT_STRIDE) == 0) ? 8 : 0;
    }
    if (idx < BH) {
        __nv_bfloat16 z = __float2bfloat16(0.0f);
        g_H[0][idx] = z;
        g_H[1][idx] = z;
    }
}

// ---------------- the persistent LSTM kernel --------------------------------
// 128 CTAs (64/layer), 256 threads. Weights in registers.
// Sync: split counters cnt[L][t][g] (g = k-group). Producer s REDs once to
// group s>>3 (8 REDs/counter -> ~220cyc drain). Consumer warp ks polls ONE
// counter. Per-warp waits: no CTA barrier in the load path.
#define SMEM_ACT_BYTES (32 * KPAD * 2)
#define SMEM_BYTES     (SMEM_ACT_BYTES + 8 * 32 * 33 * 4)

__global__ void __launch_bounds__(256, 1) lstm_kernel() {
    extern __shared__ unsigned char smem_raw[];
    __nv_bfloat16* Ash  = (__nv_bfloat16*)smem_raw;
    float*         Psum = (float*)(smem_raw + SMEM_ACT_BYTES);
    uint32_t ash_s = (uint32_t)__cvta_generic_to_shared(Ash);

    const int tid = threadIdx.x;
    const int cta = blockIdx.x;
    const int L = cta >> 6;
    const int s = cta & 63;

    const int ks   = tid >> 5;          // warp = k-slice
    const int lane = tid & 31;
    const int gid  = lane >> 2;
    const int t4   = lane & 3;

    // ---- load weight fragments into registers (once) ----
    const __nv_bfloat16* wsrc = g_W + (size_t)cta * 32 * KK;
    uint32_t areg[2][4][2][4];          // [half][kc][mb][frag]
#pragma unroll
    for (int half = 0; half < 2; ++half)
#pragma unroll
        for (int kc = 0; kc < 4; ++kc) {
            int k0 = half * 512 + ks * 64 + kc * 16 + t4 * 2;
#pragma unroll
            for (int mb = 0; mb < 2; ++mb) {
                int r = mb * 16 + gid;
                areg[half][kc][mb][0] = *(const uint32_t*)(wsrc + r * KK + k0);
                areg[half][kc][mb][1] = *(const uint32_t*)(wsrc + (r + 8) * KK + k0);
                areg[half][kc][mb][2] = *(const uint32_t*)(wsrc + r * KK + k0 + 8);
                areg[half][kc][mb][3] = *(const uint32_t*)(wsrc + (r + 8) * KK + k0 + 8);
            }
        }

    // ---- bias + cell state in registers ----
    const int bact = tid >> 3, jact = tid & 7;      // tid = b*8 + j
    float bias_r[4];
#pragma unroll
    for (int g = 0; g < 4; ++g) bias_r[g] = g_bias[cta * 32 + g * 8 + jact];
    float c_reg = 0.0f;

    int* cnt_own = g_cnt2 + L * CNT_PER_L;
    int* cnt_l0  = g_cnt2;
    // this warp's counters: (t*8 + ks) * CNT_STRIDE
    // publish counter for this CTA: group s>>3

    // per-warp cp.async lane mapping
    const int c8   = lane & 7;
    const int brow = lane >> 3;
    const int kcol = ks * 64 + c8 * 8;
    const int xdst = (brow * KPAD + kcol);
    const int hdst = (brow * KPAD + 512 + kcol);

    // ---- prologue: prefetch x(1) (per-warp wait for L1) ----
    if (L == 1) wait_cnt8(cnt_l0 + (1 * 8 + ks) * CNT_STRIDE, lane);
    {
        const __nv_bfloat16* srcx = (L == 0) ? g_X : (g_H[0] + (size_t)BH);
#pragma unroll
        for (int r = 0; r < 8; ++r)
            cp16(ash_s + (xdst + r * 4 * KPAD) * 2, srcx + (brow + r * 4) * 512 + kcol);
        cp_commit();
    }

    for (int t = 1; t <= TT; ++t) {
        float acc[2][4][4];
#pragma unroll
        for (int mb = 0; mb < 2; ++mb)
#pragma unroll
            for (int nt = 0; nt < 4; ++nt)
#pragma unroll
                for (int i = 0; i < 4; ++i) acc[mb][nt][i] = 0.0f;

        // ---- x(t) ready (prefetched) ----
        cp_wait<0>();
        __syncwarp();

        // ---- x-mma kc 0..1 ----
#pragma unroll
        for (int kc = 0; kc < 2; ++kc) {
            int k0 = ks * 64 + kc * 16 + t4 * 2;
#pragma unroll
            for (int nt = 0; nt < 4; ++nt) {
                const __nv_bfloat16* bp = Ash + (nt * 8 + gid) * KPAD + k0;
                uint32_t b0 = *(const uint32_t*)bp;
                uint32_t b1 = *(const uint32_t*)(bp + 8);
                mma16816(acc[0][nt], areg[0][kc][0], b0, b1);
                mma16816(acc[1][nt], areg[0][kc][1], b0, b1);
            }
        }

        // ---- per-warp wait on own-layer h(t-1) group counter, issue h ----
        wait_cnt8(cnt_own + ((t - 1) * 8 + ks) * CNT_STRIDE, lane);
        {
            const __nv_bfloat16* srch = g_H[L] + (size_t)(t - 1) * BH;
#pragma unroll
            for (int r = 0; r < 8; ++r)
                cp16(ash_s + (hdst + r * 4 * KPAD) * 2, srch + (brow + r * 4) * 512 + kcol);
            cp_commit();
        }

        // ---- x-mma kc 2..3 (hides h load latency) ----
#pragma unroll
        for (int kc = 2; kc < 4; ++kc) {
            int k0 = ks * 64 + kc * 16 + t4 * 2;
#pragma unroll
            for (int nt = 0; nt < 4; ++nt) {
                const __nv_bfloat16* bp = Ash + (nt * 8 + gid) * KPAD + k0;
                uint32_t b0 = *(const uint32_t*)bp;
                uint32_t b1 = *(const uint32_t*)(bp + 8);
                mma16816(acc[0][nt], areg[0][kc][0], b0, b1);
                mma16816(acc[1][nt], areg[0][kc][1], b0, b1);
            }
        }

        // ---- L0: prefetch x(t+1) NOW (static data, no wait). wait<1> keeps it in flight.
        if (L == 0 && t < TT) {
            const __nv_bfloat16* srcx = g_X + (size_t)t * BH;
#pragma unroll
            for (int r = 0; r < 8; ++r)
                cp16(ash_s + (xdst + r * 4 * KPAD) * 2, srcx + (brow + r * 4) * 512 + kcol);
            cp_commit();
            cp_wait<1>();      // h group done; x(t+1) may stay pending
        } else {
            cp_wait<0>();
        }
        __syncwarp();

        // ---- h-half MMA ----
#pragma unroll
        for (int kc = 0; kc < 4; ++kc) {
            int k0 = 512 + ks * 64 + kc * 16 + t4 * 2;
#pragma unroll
            for (int nt = 0; nt < 4; ++nt) {
                const __nv_bfloat16* bp = Ash + (nt * 8 + gid) * KPAD + k0;
                uint32_t b0 = *(const uint32_t*)bp;
                uint32_t b1 = *(const uint32_t*)(bp + 8);
                mma16816(acc[0][nt], areg[1][kc][0], b0, b1);
                mma16816(acc[1][nt], areg[1][kc][1], b0, b1);
            }
        }

        // ---- write k-partials ----
#pragma unroll
        for (int mb = 0; mb < 2; ++mb)
#pragma unroll
            for (int nt = 0; nt < 4; ++nt) {
                int r = ks * 32 + mb * 16 + gid;
                int c = nt * 8 + t4 * 2;
                Psum[r * 33 + c]           = acc[mb][nt][0];
                Psum[r * 33 + c + 1]       = acc[mb][nt][1];
                Psum[(r + 8) * 33 + c]     = acc[mb][nt][2];
                Psum[(r + 8) * 33 + c + 1] = acc[mb][nt][3];
            }
        __syncthreads();

        // ---- reduce + cell update: thread (b = tid>>3, j = tid&7) ----
        {
            float gv[4];
#pragma unroll
            for (int g = 0; g < 4; ++g) {
                int row = g * 8 + jact;
                float v = bias_r[g];
#pragma unroll
                for (int w = 0; w < 8; ++w) v += Psum[(w * 32 + row) * 33 + bact];
                gv[g] = v;
            }
            float ig = sig_fast(gv[0]);
            float fg = sig_fast(gv[1]);
            float gg = tanh_fast(gv[2]);
            float og = sig_fast(gv[3]);
            c_reg = fg * c_reg + ig * gg;
            float h_new = og * tanh_fast(c_reg);
            g_H[L][(size_t)t * BH + bact * 512 + s * 8 + jact] = __float2bfloat16(h_new);
        }
        __syncthreads();   // all h stores done (also protects Psum reuse)

        // ---- publish: single RED to this CTA's group counter (8 REDs/addr) ----
        if (tid == 0) red_rel(cnt_own + (t * 8 + (s >> 3)) * CNT_STRIDE);

        // ---- L1: prefetch x(t+1) after publish (needs h0(t+1)) ----
        if (L == 1 && t < TT) {
            wait_cnt8(cnt_l0 + ((t + 1) * 8 + ks) * CNT_STRIDE, lane);
            const __nv_bfloat16* srcx = g_H[0] + (size_t)(t + 1) * BH;
#pragma unroll
            for (int r = 0; r < 8; ++r)
                cp16(ash_s + (xdst + r * 4 * KPAD) * 2, srcx + (brow + r * 4) * 512 + kcol);
            cp_commit();
        }
    }
}

// ---------------- final FC + sigmoid ----------------------------------------
__global__ void fc_kernel(const float* __restrict__ fc_w,
                          const float* __restrict__ fc_b,
                          float* __restrict__ out) {
    __shared__ float part[512];
    int tid = threadIdx.x;                 // 512 threads: (b, o, p8)
    int p = tid & 7, o = (tid >> 3) & 1, b = tid >> 4;
    const __nv_bfloat16* h = g_H[1] + (size_t)TT * BH + b * 512 + p * 64;
    const float* w = fc_w + o * 512 + p * 64;
    float sum = 0.0f;
#pragma unroll
    for (int u = 0; u < 64; ++u) sum += __bfloat162float(h[u]) * w[u];
    part[tid] = sum;
    __syncthreads();
    if (p == 0) {
        float v = fc_b[o];
#pragma unroll
        for (int q = 0; q < 8; ++q) v += part[tid + q];
        out[b * 2 + o] = 1.0f / (1.0f + __expf(-v));
    }
}

// ---------------- launch -----------------------------------------------------
extern "C" void kernel_launch(void* const* d_in, const int* in_sizes, int n_in,
                              void* d_out, int out_size) {
    const int*   tokens = (const int*)d_in[0];
    const float* emb    = (const float*)d_in[1];
    const float* w_ih   = (const float*)d_in[2];
    const float* w_hh   = (const float*)d_in[3];
    const float* b_ih   = (const float*)d_in[4];
    const float* b_hh   = (const float*)d_in[5];
    const float* fc_w   = (const float*)d_in[6];
    const float* fc_b   = (const float*)d_in[7];
    float* out = (float*)d_out;

    cudaFuncSetAttribute(lstm_kernel, cudaFuncAttributeMaxDynamicSharedMemorySize, SMEM_BYTES);

    prep_w_kernel<<<16384, 256>>>(w_ih, w_hh, b_ih, b_hh);
    gather_x_kernel<<<16384, 256>>>(tokens, emb);
    init_kernel<<<(2 * CNT_PER_L + 255) / 256, 256>>>();
    lstm_kernel<<<NCTA, 256, SMEM_BYTES>>>();
    fc_kernel<<<1, 512>>>(fc_w, fc_b, out);
}